// round 15
// baseline (speedup 1.0000x reference)
#include <cuda_runtime.h>
#include <cuda_fp16.h>
#include <cstdint>

#define MTOT 32768
#define DTOT 128
#define HTOT 256
#define TOTP 25
#define NP2  24            // stored params per dynamic dim (u_w8,u_h8,u_d0..7)
#define NDYN 64
#define NSTA 64
#define N2P  (NDYN * NP2)  // 1536
#define NTILE 96           // 4 dims * 24
#define W2S  3200

// ---------------- scratch (device globals: allocation-free) ----------------
__device__ __half g_xs_hi[MTOT * NSTA];   // x static cols [m][ks] fp16 hi
__device__ __half g_xs_lo[MTOT * NSTA];
__device__ __half g_w1_hi[HTOT * NSTA];   // W1 static rows [n][ks]
__device__ __half g_w1_lo[HTOT * NSTA];
__device__ __half g_hA_hi[MTOT * HTOT];   // hidden [m][h] fp16 hi
__device__ __half g_hA_lo[MTOT * HTOT];
__device__ __half g_wB_hi[N2P * HTOT];    // W2 dyn cols (24/dim) [n][k]
__device__ __half g_wB_lo[N2P * HTOT];
__device__ __half g_wd8_hi[NDYN * HTOT];  // W2 col j=24 per dim, [n][k] fp16
__device__ __half g_wd8_lo[NDYN * HTOT];
__device__ float g_b24[NDYN];
__device__ float g_d8[NDYN * MTOT];
__device__ float g_b2d[N2P];
__device__ float g_ld4[16 * MTOT];        // per-4-dim-group logdet partials
__device__ int   g_dyn_map[NDYN];
__device__ int   g_stat_map[NSTA];
__device__ float g_stat_mv[NSTA];
__device__ int   g_pos[DTOT];             // d -> static position, or -1
__device__ int   g_n_dyn;
__device__ int   g_n_stat;

// ---------------- helpers ----------------
__device__ __forceinline__ float softplus_f(float v) {
    return fmaxf(v, 0.f) + log1pf(expf(-fabsf(v)));
}
__device__ __forceinline__ uint32_t smem_u32(const void* p) {
    uint32_t a;
    asm("{ .reg .u64 t; cvta.to.shared.u64 t, %1; cvt.u32.u64 %0, t; }" : "=r"(a) : "l"(p));
    return a;
}
__device__ __forceinline__ uint32_t packh(__half a, __half b) {
    __half2 t; t.x = a; t.y = b;
    return *(uint32_t*)&t;
}
__device__ __forceinline__ void split_h(float v, __half& hi, __half& lo) {
    hi = __float2half_rn(v);
    lo = __float2half_rn(v - __half2float(hi));
}
#define LDSM_X4(r0, r1, r2, r3, addr)                                          \
    asm volatile("ldmatrix.sync.aligned.m8n8.x4.shared.b16 {%0,%1,%2,%3}, [%4];" \
                 : "=r"(r0), "=r"(r1), "=r"(r2), "=r"(r3) : "r"(addr))
#define CP_ASYNC16(dst, src)                                                   \
    asm volatile("cp.async.cg.shared.global [%0], [%1], 16;" :: "r"(dst), "l"(src))
#define CP_COMMIT() asm volatile("cp.async.commit_group;" ::: "memory")

__device__ __forceinline__ void mma16816(float* d, const uint32_t* a,
                                         uint32_t b0, uint32_t b1) {
    asm volatile(
        "mma.sync.aligned.m16n8k16.row.col.f32.f16.f16.f32 "
        "{%0,%1,%2,%3}, {%4,%5,%6,%7}, {%8,%9}, {%0,%1,%2,%3};"
        : "+f"(d[0]), "+f"(d[1]), "+f"(d[2]), "+f"(d[3])
        : "r"(a[0]), "r"(a[1]), "r"(a[2]), "r"(a[3]), "r"(b0), "r"(b1));
}
// fp16-accumulating variant — used only for lo-correction terms
__device__ __forceinline__ void mma16816h(uint32_t* d, const uint32_t* a,
                                          uint32_t b0, uint32_t b1) {
    asm volatile(
        "mma.sync.aligned.m16n8k16.row.col.f16.f16.f16.f16 "
        "{%0,%1}, {%2,%3,%4,%5}, {%6,%7}, {%0,%1};"
        : "+r"(d[0]), "+r"(d[1])
        : "r"(a[0]), "r"(a[1]), "r"(a[2]), "r"(a[3]), "r"(b0), "r"(b1));
}

// ---------------- setup (parallel) ----------------
__global__ void k_setup(const float* __restrict__ mask) {
    __shared__ int pd[DTOT], ps[DTOT];
    __shared__ int s_nd, s_ns;
    int d = threadIdx.x;                      // 0..127
    float mv = mask[d];
    int isdyn = (mv == 0.0f) ? 1 : 0;
    pd[d] = isdyn;
    ps[d] = 1 - isdyn;
    __syncthreads();
    if (d == 0) {
        int cd = 0, cs = 0;
        for (int i = 0; i < DTOT; i++) {
            int t = pd[i]; pd[i] = cd; cd += t;
            int u = ps[i]; ps[i] = cs; cs += u;
        }
        s_nd = cd; s_ns = cs < NSTA ? cs : NSTA;
        g_n_dyn = cd; g_n_stat = s_ns;
    }
    __syncthreads();
    if (isdyn) {
        if (pd[d] < NDYN) g_dyn_map[pd[d]] = d;
        g_pos[d] = -1;
    } else {
        int p = ps[d];
        if (p < NSTA) { g_stat_map[p] = d; g_stat_mv[p] = mv; }
        g_pos[d] = (p < NSTA) ? p : -1;
    }
    int nd = s_nd, ns = s_ns;
    if (d < NDYN && d >= nd) g_dyn_map[d] = 0;
    if (d < NSTA && d >= ns) { g_stat_map[d] = 0; g_stat_mv[d] = 0.f; }
}

// ---- merged prep: cvtB + b2 + d8w(fp16) + W1 + passx ------------------------
#define NB_CVTB (48 * 8)
#define PB_BASE (NB_CVTB + 6 + 64 + 64)      // 518
#define NB_PASS ((MTOT * DTOT / 4) / 256)    // 4096
__global__ __launch_bounds__(256) void k_prep_all(const float* __restrict__ W2,
                                                  const float* __restrict__ b2,
                                                  const float* __restrict__ W1,
                                                  const float4* __restrict__ x4,
                                                  const float* __restrict__ mask,
                                                  float4* __restrict__ out4) {
    int bid = blockIdx.x, tid = threadIdx.x;
    if (bid >= PB_BASE) {
        int i = (bid - PB_BASE) * 256 + tid;
        float4 v = x4[i];
        int m = i >> 5;
        int c = (i & 31) * 4;
        float4 mk = *(const float4*)&mask[c];
        float4 o;
        o.x = v.x * mk.x; o.y = v.y * mk.y; o.z = v.z * mk.z; o.w = v.w * mk.w;
        out4[i] = o;
        const float* vv = (const float*)&v;
        const float* mm = (const float*)&mk;
#pragma unroll
        for (int j = 0; j < 4; j++) {
            int pos = g_pos[c + j];
            if (pos >= 0) {
                float sv = vv[j] * mm[j];
                __half hi, lo; split_h(sv, hi, lo);
                g_xs_hi[(size_t)m * NSTA + pos] = hi;
                g_xs_lo[(size_t)m * NSTA + pos] = lo;
            }
        }
    } else if (bid < NB_CVTB) {
        __shared__ float t[32][33];
        int n0 = (bid % 48) * 32, k0 = (bid / 48) * 32;
        int tx = tid & 31, ty = tid >> 5;
        int n = n0 + tx;
        int dd = n / NP2, j = n - dd * NP2;
        int col = (dd < g_n_dyn) ? (g_dyn_map[dd] * TOTP + j) : -1;
#pragma unroll
        for (int i = 0; i < 4; i++) {
            int k = k0 + ty + 8 * i;
            t[tx][ty + 8 * i] = (col >= 0) ? W2[(size_t)k * W2S + col] : 0.f;
        }
        __syncthreads();
#pragma unroll
        for (int i = 0; i < 4; i++) {
            int nn = n0 + ty + 8 * i;
            float v = t[ty + 8 * i][tx];
            __half hi, lo; split_h(v, hi, lo);
            g_wB_hi[(size_t)nn * HTOT + k0 + tx] = hi;
            g_wB_lo[(size_t)nn * HTOT + k0 + tx] = lo;
        }
    } else if (bid < NB_CVTB + 6) {
        int n = (bid - NB_CVTB) * 256 + tid;
        if (n < N2P) {
            int dd = n / NP2, j = n - dd * NP2;
            g_b2d[n] = (dd < g_n_dyn) ? b2[g_dyn_map[dd] * TOTP + j] : 0.f;
        }
    } else if (bid < NB_CVTB + 6 + 64) {
        int idx = (bid - NB_CVTB - 6) * 256 + tid;   // n*256+k
        int n = idx >> 8, k = idx & 255;
        float v = W2[(size_t)k * W2S + g_dyn_map[n] * TOTP + 24];
        __half hi, lo; split_h(v, hi, lo);
        g_wd8_hi[idx] = hi;
        g_wd8_lo[idx] = lo;
        if (idx < NDYN) g_b24[idx] = b2[g_dyn_map[idx] * TOTP + 24];
    } else {
        int idx = (bid - NB_CVTB - 6 - 64) * 256 + tid;
        int k = idx & 63, n = idx >> 6;
        float v = (k < g_n_stat) ? W1[(size_t)g_stat_map[k] * HTOT + n] : 0.f;
        __half hi, lo; split_h(v, hi, lo);
        g_w1_hi[(size_t)n * NSTA + k] = hi;
        g_w1_lo[(size_t)n * NSTA + k] = lo;
    }
}

// ---- GEMM1 via mma.sync fp16 3-term: hidden = relu(xs@w1^T + b1) ------------
#define O1_A_HI 0
#define O1_A_LO 16384
#define O1_B_HI 32768
#define O1_B_LO 49152
#define SM1_BYTES 65536

__global__ __launch_bounds__(256, 2) void k_gemm1(const float* __restrict__ b1) {
    extern __shared__ __align__(16) char smem[];
    const uint32_t sb = smem_u32(smem);
    const int tid = threadIdx.x, wid = tid >> 5, lane = tid & 31;
    const int mbase = blockIdx.x * 128, nbase = blockIdx.y * 128;
    const int warpM = wid & 3, warpN = wid >> 2;

    const int r_ld = tid >> 3, c_ld = tid & 7;
#pragma unroll
    for (int i = 0; i < 4; i++) {
        int r = r_ld + 32 * i;
        uint32_t sw = r * 128 + ((c_ld ^ (r & 7)) << 4);
        size_t ga = (size_t)(mbase + r) * NSTA + c_ld * 8;
        size_t gb = (size_t)(nbase + r) * NSTA + c_ld * 8;
        CP_ASYNC16(sb + O1_A_HI + sw, (const char*)&g_xs_hi[ga]);
        CP_ASYNC16(sb + O1_A_LO + sw, (const char*)&g_xs_lo[ga]);
        CP_ASYNC16(sb + O1_B_HI + sw, (const char*)&g_w1_hi[gb]);
        CP_ASYNC16(sb + O1_B_LO + sw, (const char*)&g_w1_lo[gb]);
    }
    CP_COMMIT();

    float acc[2][8][4];
#pragma unroll
    for (int mt = 0; mt < 2; mt++)
#pragma unroll
        for (int nt = 0; nt < 8; nt++)
#pragma unroll
            for (int r = 0; r < 4; r++) acc[mt][nt][r] = 0.f;

    const int tsel = lane >> 3, rowin = lane & 7;
    const int tshalf = (tsel & 1) * 8, tkhalf = tsel >> 1;

    asm volatile("cp.async.wait_group 0;" ::: "memory");
    __syncthreads();

#pragma unroll
    for (int s = 0; s < 4; ++s) {
        const int kch = s * 2 + tkhalf;
        uint32_t aH[2][4], aL[2][4];
#pragma unroll
        for (int mt = 0; mt < 2; mt++) {
            int r = warpM * 32 + mt * 16 + tshalf + rowin;
            uint32_t off = r * 128 + ((kch ^ (r & 7)) << 4);
            LDSM_X4(aH[mt][0], aH[mt][1], aH[mt][2], aH[mt][3], sb + O1_A_HI + off);
            LDSM_X4(aL[mt][0], aL[mt][1], aL[mt][2], aL[mt][3], sb + O1_A_LO + off);
        }
        uint32_t bH[8][2], bL[8][2];
#pragma unroll
        for (int ng = 0; ng < 4; ng++) {
            int r = warpN * 64 + ng * 16 + tshalf + rowin;
            uint32_t off = r * 128 + ((kch ^ (r & 7)) << 4);
            uint32_t q0, q1, q2, q3;
            LDSM_X4(q0, q1, q2, q3, sb + O1_B_HI + off);
            bH[ng * 2][0] = q0; bH[ng * 2 + 1][0] = q1;
            bH[ng * 2][1] = q2; bH[ng * 2 + 1][1] = q3;
            LDSM_X4(q0, q1, q2, q3, sb + O1_B_LO + off);
            bL[ng * 2][0] = q0; bL[ng * 2 + 1][0] = q1;
            bL[ng * 2][1] = q2; bL[ng * 2 + 1][1] = q3;
        }
#pragma unroll
        for (int mt = 0; mt < 2; mt++)
#pragma unroll
            for (int nt = 0; nt < 8; nt++) {
                mma16816(acc[mt][nt], aH[mt], bH[nt][0], bH[nt][1]);
                mma16816(acc[mt][nt], aH[mt], bL[nt][0], bL[nt][1]);
                mma16816(acc[mt][nt], aL[mt], bH[nt][0], bH[nt][1]);
            }
    }

    // epilogue: +b1, relu, fp16 split, store [m][h]
    const int mrow = warpM * 32 + (lane >> 2);
    const int ncol0 = warpN * 64 + 2 * (lane & 3);
    float bb[8][2];
#pragma unroll
    for (int nt = 0; nt < 8; nt++) {
        bb[nt][0] = __ldg(&b1[nbase + ncol0 + nt * 8]);
        bb[nt][1] = __ldg(&b1[nbase + ncol0 + nt * 8 + 1]);
    }
#pragma unroll
    for (int mt = 0; mt < 2; mt++) {
#pragma unroll
        for (int nt = 0; nt < 8; nt++) {
            int m0 = mbase + mrow + mt * 16;
            int c = nbase + ncol0 + nt * 8;
            float f0 = fmaxf(acc[mt][nt][0] + bb[nt][0], 0.f);
            float f1 = fmaxf(acc[mt][nt][1] + bb[nt][1], 0.f);
            float f2 = fmaxf(acc[mt][nt][2] + bb[nt][0], 0.f);
            float f3 = fmaxf(acc[mt][nt][3] + bb[nt][1], 0.f);
            __half h0, l0, h1, l1, h2, l2, h3, l3;
            split_h(f0, h0, l0); split_h(f1, h1, l1);
            split_h(f2, h2, l2); split_h(f3, h3, l3);
            *(uint32_t*)&g_hA_hi[(size_t)m0 * HTOT + c]       = packh(h0, h1);
            *(uint32_t*)&g_hA_lo[(size_t)m0 * HTOT + c]       = packh(l0, l1);
            *(uint32_t*)&g_hA_hi[(size_t)(m0 + 8) * HTOT + c] = packh(h2, h3);
            *(uint32_t*)&g_hA_lo[(size_t)(m0 + 8) * HTOT + c] = packh(l2, l3);
        }
    }
}

// ---- d8 via mma.sync fp16 3-term: g_d8[dd][m] = hidden@wd8^T + b24 ----------
#define OD_A_HI 0
#define OD_A_LO 16384
#define OD_B_HI 32768
#define OD_B_LO 40960
#define SMD_STG 49152
#define SMD_BYTES (2 * SMD_STG)   // 96KB -> 2 CTAs/SM

__global__ __launch_bounds__(256, 2) void k_d8_mma() {
    extern __shared__ __align__(16) char smem[];
    const uint32_t sb = smem_u32(smem);
    const int tid = threadIdx.x, wid = tid >> 5, lane = tid & 31;
    const int mbase = blockIdx.x * 128;
    const int warpM = wid & 3, warpN = wid >> 2;

    float acc[2][4][4];
#pragma unroll
    for (int mt = 0; mt < 2; mt++)
#pragma unroll
        for (int nt = 0; nt < 4; nt++)
#pragma unroll
            for (int r = 0; r < 4; r++) acc[mt][nt][r] = 0.f;

    const int tsel = lane >> 3, rowin = lane & 7;
    const int tshalf = (tsel & 1) * 8, tkhalf = tsel >> 1;
    const int r_ld = tid >> 3, c_ld = tid & 7;

    auto prefetch = [&](int kc, int b) {
        uint32_t base = sb + b * SMD_STG;
#pragma unroll
        for (int i = 0; i < 4; i++) {
            int r = r_ld + 32 * i;
            uint32_t sw = r * 128 + ((c_ld ^ (r & 7)) << 4);
            size_t ga = (size_t)(mbase + r) * HTOT + kc * 64 + c_ld * 8;
            CP_ASYNC16(base + OD_A_HI + sw, (const char*)&g_hA_hi[ga]);
            CP_ASYNC16(base + OD_A_LO + sw, (const char*)&g_hA_lo[ga]);
        }
#pragma unroll
        for (int i = 0; i < 2; i++) {
            int r = r_ld + 32 * i;
            uint32_t sw = r * 128 + ((c_ld ^ (r & 7)) << 4);
            size_t gb = (size_t)r * HTOT + kc * 64 + c_ld * 8;
            CP_ASYNC16(base + OD_B_HI + sw, (const char*)&g_wd8_hi[gb]);
            CP_ASYNC16(base + OD_B_LO + sw, (const char*)&g_wd8_lo[gb]);
        }
        CP_COMMIT();
    };

    prefetch(0, 0);
#pragma unroll 1
    for (int kc = 0; kc < 4; ++kc) {
        // wait for chunk kc, align warps, THEN prefetch kc+1 (buffer provably free)
        if (kc > 0) asm volatile("cp.async.wait_group 1;" ::: "memory");
        else        asm volatile("cp.async.wait_group 0;" ::: "memory");
        __syncthreads();
        if (kc < 3) prefetch(kc + 1, (kc + 1) & 1);
        const uint32_t base = sb + (kc & 1) * SMD_STG;
#pragma unroll
        for (int s = 0; s < 4; ++s) {
            const int kch = s * 2 + tkhalf;
            uint32_t aH[2][4], aL[2][4];
#pragma unroll
            for (int mt = 0; mt < 2; mt++) {
                int r = warpM * 32 + mt * 16 + tshalf + rowin;
                uint32_t off = r * 128 + ((kch ^ (r & 7)) << 4);
                LDSM_X4(aH[mt][0], aH[mt][1], aH[mt][2], aH[mt][3], base + OD_A_HI + off);
                LDSM_X4(aL[mt][0], aL[mt][1], aL[mt][2], aL[mt][3], base + OD_A_LO + off);
            }
            uint32_t bH[4][2], bL[4][2];
#pragma unroll
            for (int ng = 0; ng < 2; ng++) {
                int r = warpN * 32 + ng * 16 + tshalf + rowin;
                uint32_t off = r * 128 + ((kch ^ (r & 7)) << 4);
                uint32_t q0, q1, q2, q3;
                LDSM_X4(q0, q1, q2, q3, base + OD_B_HI + off);
                bH[ng * 2][0] = q0; bH[ng * 2 + 1][0] = q1;
                bH[ng * 2][1] = q2; bH[ng * 2 + 1][1] = q3;
                LDSM_X4(q0, q1, q2, q3, base + OD_B_LO + off);
                bL[ng * 2][0] = q0; bL[ng * 2 + 1][0] = q1;
                bL[ng * 2][1] = q2; bL[ng * 2 + 1][1] = q3;
            }
#pragma unroll
            for (int mt = 0; mt < 2; mt++)
#pragma unroll
                for (int nt = 0; nt < 4; nt++) {
                    mma16816(acc[mt][nt], aH[mt], bH[nt][0], bH[nt][1]);
                    mma16816(acc[mt][nt], aH[mt], bL[nt][0], bL[nt][1]);
                    mma16816(acc[mt][nt], aL[mt], bH[nt][0], bH[nt][1]);
                }
        }
    }

    const int mrow = warpM * 32 + (lane >> 2);
    const int ncol0 = warpN * 32 + 2 * (lane & 3);
#pragma unroll
    for (int mt = 0; mt < 2; mt++) {
#pragma unroll
        for (int nt = 0; nt < 4; nt++) {
            int m0 = mbase + mrow + mt * 16;
            int n = ncol0 + nt * 8;
            float b0 = g_b24[n], b1v = g_b24[n + 1];
            g_d8[(size_t)n * MTOT + m0]           = acc[mt][nt][0] + b0;
            g_d8[(size_t)(n + 1) * MTOT + m0]     = acc[mt][nt][1] + b1v;
            g_d8[(size_t)n * MTOT + m0 + 8]       = acc[mt][nt][2] + b0;
            g_d8[(size_t)(n + 1) * MTOT + m0 + 8] = acc[mt][nt][3] + b1v;
        }
    }
}

// ---- GEMM2 (fp16 3-term, corrections in fp16-acc HMMA) + fused spline -------
#define STG 57344
#define OFF_A_HI 0
#define OFF_A_LO 16384
#define OFF_B_HI 32768
#define OFF_B_LO 45056
#define SM2_BYTES (2 * STG)
#define SMF_LD  (96 * 132)     // float offset of logdet-partial region

__global__ __launch_bounds__(256, 2) void k_gemm2_fused(const float* __restrict__ x,
                                                        float* __restrict__ out) {
    extern __shared__ __align__(16) char smem[];
    const uint32_t sb = smem_u32(smem);
    const int tid = threadIdx.x, wid = tid >> 5, lane = tid & 31;
    const int mbase = blockIdx.x * 128, nbase = blockIdx.y * NTILE;
    const int warpM = wid & 3, warpN = wid >> 2;

    float acc[2][6][4];         // main hi*hi term, fp32 acc
    uint32_t accC[2][6][2];     // corrections (hi*lo + lo*hi), fp16x2 acc
#pragma unroll
    for (int mt = 0; mt < 2; mt++)
#pragma unroll
        for (int nt = 0; nt < 6; nt++) {
#pragma unroll
            for (int r = 0; r < 4; r++) acc[mt][nt][r] = 0.f;
            accC[mt][nt][0] = 0u; accC[mt][nt][1] = 0u;
        }

    const int tsel = lane >> 3, rowin = lane & 7;
    const int tshalf = (tsel & 1) * 8, tkhalf = tsel >> 1;
    const int r_ld = tid >> 3, c_ld = tid & 7;

    auto prefetch = [&](int kc, int b) {
        uint32_t base = sb + b * STG;
#pragma unroll
        for (int i = 0; i < 4; i++) {
            int r = r_ld + 32 * i;
            uint32_t sw = r * 128 + ((c_ld ^ (r & 7)) << 4);
            size_t ga = (size_t)(mbase + r) * HTOT + kc * 64 + c_ld * 8;
            CP_ASYNC16(base + OFF_A_HI + sw, (const char*)&g_hA_hi[ga]);
            CP_ASYNC16(base + OFF_A_LO + sw, (const char*)&g_hA_lo[ga]);
        }
#pragma unroll
        for (int i = 0; i < 3; i++) {
            int r = r_ld + 32 * i;
            uint32_t sw = r * 128 + ((c_ld ^ (r & 7)) << 4);
            size_t gb = (size_t)(nbase + r) * HTOT + kc * 64 + c_ld * 8;
            CP_ASYNC16(base + OFF_B_HI + sw, (const char*)&g_wB_hi[gb]);
            CP_ASYNC16(base + OFF_B_LO + sw, (const char*)&g_wB_lo[gb]);
        }
        CP_COMMIT();
    };

    prefetch(0, 0);
#pragma unroll 1
    for (int kc = 0; kc < 4; ++kc) {
        // wait for chunk kc, align warps, THEN prefetch kc+1 (buffer provably free)
        if (kc > 0) asm volatile("cp.async.wait_group 1;" ::: "memory");
        else        asm volatile("cp.async.wait_group 0;" ::: "memory");
        __syncthreads();
        if (kc < 3) prefetch(kc + 1, (kc + 1) & 1);
        const uint32_t base = sb + (kc & 1) * STG;
#pragma unroll
        for (int s = 0; s < 4; ++s) {
            const int kch = s * 2 + tkhalf;
            uint32_t aH[2][4], aL[2][4];
#pragma unroll
            for (int mt = 0; mt < 2; mt++) {
                int r = warpM * 32 + mt * 16 + tshalf + rowin;
                uint32_t off = r * 128 + ((kch ^ (r & 7)) << 4);
                LDSM_X4(aH[mt][0], aH[mt][1], aH[mt][2], aH[mt][3], base + OFF_A_HI + off);
                LDSM_X4(aL[mt][0], aL[mt][1], aL[mt][2], aL[mt][3], base + OFF_A_LO + off);
            }
            // load B per-ng to cap register pressure
#pragma unroll
            for (int ng = 0; ng < 3; ng++) {
                int r = warpN * 48 + ng * 16 + tshalf + rowin;
                uint32_t off = r * 128 + ((kch ^ (r & 7)) << 4);
                uint32_t bh0, bh1, bh2, bh3, bl0, bl1, bl2, bl3;
                LDSM_X4(bh0, bh1, bh2, bh3, base + OFF_B_HI + off);
                LDSM_X4(bl0, bl1, bl2, bl3, base + OFF_B_LO + off);
#pragma unroll
                for (int mt = 0; mt < 2; mt++) {
                    mma16816(acc[mt][ng * 2],     aH[mt], bh0, bh2);
                    mma16816(acc[mt][ng * 2 + 1], aH[mt], bh1, bh3);
                    mma16816h(accC[mt][ng * 2],     aH[mt], bl0, bl2);
                    mma16816h(accC[mt][ng * 2 + 1], aH[mt], bl1, bl3);
                    mma16816h(accC[mt][ng * 2],     aL[mt], bh0, bh2);
                    mma16816h(accC[mt][ng * 2 + 1], aL[mt], bh1, bh3);
                }
            }
        }
    }

    // hoist spline's global loads: overlap latency with staging barrier below
    const int m_l = tid & 127;
    const int m = mbase + m_l;
    float xd_pre[2], d8_pre[2];
    int   d_pre[2];
#pragma unroll
    for (int i = 0; i < 2; ++i) {
        int ddl = (tid >> 7) + 2 * i;
        int dd = blockIdx.y * 4 + ddl;
        bool ok = (dd < g_n_dyn);
        int d = ok ? g_dyn_map[dd] : 0;
        d_pre[i]  = ok ? d : -1;
        xd_pre[i] = ok ? x[(size_t)m * DTOT + d] : 0.f;
        d8_pre[i] = ok ? g_d8[(size_t)dd * MTOT + m] : 0.f;
    }

    __syncthreads();   // all compute done before reusing smem for staging

    // -------- stage D + corrections + bias into smem [n][m], stride 132 ------
    float* smf = (float*)smem;
    {
        int mrow = warpM * 32 + (lane >> 2);
        int ncol = 2 * (lane & 3);
#pragma unroll
        for (int mt = 0; mt < 2; mt++)
#pragma unroll
            for (int nt = 0; nt < 6; nt++) {
                int mm = mrow + mt * 16;
                int n = warpN * 48 + nt * 8 + ncol;
                float b0 = g_b2d[nbase + n], b1v = g_b2d[nbase + n + 1];
                __half2 c01 = *(__half2*)&accC[mt][nt][0];
                __half2 c23 = *(__half2*)&accC[mt][nt][1];
                smf[n * 132 + mm]           = acc[mt][nt][0] + __half2float(c01.x) + b0;
                smf[(n + 1) * 132 + mm]     = acc[mt][nt][1] + __half2float(c01.y) + b1v;
                smf[n * 132 + mm + 8]       = acc[mt][nt][2] + __half2float(c23.x) + b0;
                smf[(n + 1) * 132 + mm + 8] = acc[mt][nt][3] + __half2float(c23.y) + b1v;
            }
    }
    __syncthreads();

    // -------- fused rational-quadratic spline: 4 dyn dims x 128 rows ---------
    float myld = 0.f;
#pragma unroll 1
    for (int i = 0; i < 2; ++i) {
        if (d_pre[i] < 0) continue;
        int ddl = (tid >> 7) + 2 * i;
        float xd = xd_pre[i];
        float d8 = d8_pre[i];

        const float* u = &smf[(ddl * NP2) * 132 + m_l];
#define U(j) u[(j) * 132]
        float w[8], cw[9], h[8], ch[9];
        {
            float mx = U(0);
#pragma unroll
            for (int t = 1; t < 8; t++) mx = fmaxf(mx, U(t));
            float e[8], s = 0.f;
#pragma unroll
            for (int t = 0; t < 8; t++) { e[t] = expf(U(t) - mx); s += e[t]; }
            float inv = 1.f / s, c = 0.f;
            cw[0] = -3.f;
#pragma unroll
            for (int t = 0; t < 8; t++) {
                w[t] = 0.001f + 0.992f * e[t] * inv;
                c += w[t];
                cw[t + 1] = (c - 0.5f) * 6.f;
            }
            cw[8] += 1e-6f;
        }
        {
            float mx = U(8);
#pragma unroll
            for (int t = 1; t < 8; t++) mx = fmaxf(mx, U(8 + t));
            float e[8], s = 0.f;
#pragma unroll
            for (int t = 0; t < 8; t++) { e[t] = expf(U(8 + t) - mx); s += e[t]; }
            float inv = 1.f / s, c = 0.f;
            ch[0] = -3.f;
#pragma unroll
            for (int t = 0; t < 8; t++) {
                h[t] = 0.001f + 0.992f * e[t] * inv;
                c += h[t];
                ch[t + 1] = (c - 0.5f) * 6.f;
            }
        }
        int idx = -1;
#pragma unroll
        for (int t = 0; t < 9; t++) idx += (xd >= cw[t]) ? 1 : 0;
        idx = max(0, min(7, idx));

        float ww = w[0], cwi = cw[0], hh = h[0], chi = ch[0], ud0 = U(16), ud1 = U(17);
#pragma unroll
        for (int t = 1; t < 8; t++) {
            bool sel = (idx == t);
            ww  = sel ? w[t]      : ww;
            cwi = sel ? cw[t]     : cwi;
            hh  = sel ? h[t]      : hh;
            chi = sel ? ch[t]     : chi;
            ud0 = sel ? U(16 + t) : ud0;
            ud1 = sel ? ((t == 7) ? d8 : U(17 + t)) : ud1;
        }
#undef U
        float di  = fminf(fmaxf(softplus_f(ud0) + 0.001f, 0.001f), 1000.f);
        float di1 = fminf(fmaxf(softplus_f(ud1) + 0.001f, 0.001f), 1000.f);

        float delta = hh / ww;
        float th = fminf(fmaxf((xd - cwi) / ww, 0.f), 1.f);
        float t1m = th * (1.f - th);
        float th2 = th * th;
        float num = di1 * th2 + delta * t1m;
        float den = fmaxf(delta + (di + di1 - 2.f * delta) * t1m, 1e-6f);
        float sp  = chi + delta * num / den * ww;
        float omth = 1.f - th;
        float dnum = delta * delta * (di1 * th2 + 2.f * delta * t1m + di * omth * omth);
        float sld = logf(fmaxf(dnum / (den * den), 1e-12f));

        bool inr = (xd >= -3.f) && (xd <= 3.f);
        out[(size_t)m * DTOT + d_pre[i]] = inr ? sp : xd;
        myld += inr ? sld : 0.f;
    }
    // per-4-dim-group logdet partial (deterministic fixed order)
    smf[SMF_LD + tid] = myld;
    __syncthreads();
    if (tid < 128)
        g_ld4[(size_t)blockIdx.y * MTOT + m] = smf[SMF_LD + tid] + smf[SMF_LD + tid + 128];
}

// ---------------- deterministic pairwise-tree logdet reduction (16 rows) -----
__global__ void k_reduce(float* __restrict__ outld) {
    int m = blockIdx.x * 256 + threadIdx.x;
    float a[8];
#pragma unroll
    for (int i = 0; i < 8; i++)
        a[i] = g_ld4[(size_t)(2 * i) * MTOT + m] + g_ld4[(size_t)(2 * i + 1) * MTOT + m];
#pragma unroll
    for (int w = 4; w >= 1; w >>= 1)
#pragma unroll
        for (int i = 0; i < w; i++) a[i] = a[2 * i] + a[2 * i + 1];
    outld[m] = a[0];
}

extern "C" void kernel_launch(void* const* d_in, const int* in_sizes, int n_in,
                              void* d_out, int out_size) {
    const float* x    = (const float*)d_in[0];
    const float* mask = (const float*)d_in[1];
    const float* W1   = (const float*)d_in[2];
    const float* b1   = (const float*)d_in[3];
    const float* W2   = (const float*)d_in[4];
    const float* b2   = (const float*)d_in[5];
    float* out = (float*)d_out;

    cudaFuncSetAttribute(k_gemm1, cudaFuncAttributeMaxDynamicSharedMemorySize, SM1_BYTES);
    cudaFuncSetAttribute(k_d8_mma, cudaFuncAttributeMaxDynamicSharedMemorySize, SMD_BYTES);
    cudaFuncSetAttribute(k_gemm2_fused, cudaFuncAttributeMaxDynamicSharedMemorySize, SM2_BYTES);

    k_setup<<<1, DTOT>>>(mask);
    k_prep_all<<<PB_BASE + NB_PASS, 256>>>(W2, b2, W1, (const float4*)x, mask,
                                           (float4*)out);
    k_gemm1<<<dim3(MTOT / 128, HTOT / 128), 256, SM1_BYTES>>>(b1);
    k_d8_mma<<<MTOT / 128, 256, SMD_BYTES>>>();
    k_gemm2_fused<<<dim3(MTOT / 128, N2P / NTILE), 256, SM2_BYTES>>>(x, out);
    if (out_size >= MTOT * DTOT + MTOT)
        k_reduce<<<MTOT / 256, 256>>>(out + (size_t)MTOT * DTOT);
}

// round 17
// speedup vs baseline: 1.0194x; 1.0194x over previous
#include <cuda_runtime.h>
#include <cuda_fp16.h>
#include <cstdint>

#define MTOT 32768
#define DTOT 128
#define HTOT 256
#define TOTP 25
#define NP2  24            // stored params per dynamic dim (u_w8,u_h8,u_d0..7)
#define NDYN 64
#define NSTA 64
#define N2P  (NDYN * NP2)  // 1536
#define NTILE 96           // 4 dims * 24
#define W2S  3200

// ---------------- scratch (device globals: allocation-free) ----------------
__device__ __half g_xs_hi[MTOT * NSTA];   // x static cols [m][ks] fp16 hi
__device__ __half g_xs_lo[MTOT * NSTA];
__device__ __half g_w1_hi[HTOT * NSTA];   // W1 static rows [n][ks]
__device__ __half g_w1_lo[HTOT * NSTA];
__device__ __half g_hA_hi[MTOT * HTOT];   // hidden [m][h] fp16 hi
__device__ __half g_hA_lo[MTOT * HTOT];
__device__ __half g_wB_hi[N2P * HTOT];    // W2 dyn cols (24/dim) [n][k]
__device__ __half g_wB_lo[N2P * HTOT];
__device__ __half g_wd8_hi[NDYN * HTOT];  // W2 col j=24 per dim, [n][k] fp16
__device__ __half g_wd8_lo[NDYN * HTOT];
__device__ float g_b24[NDYN];
__device__ float g_d8[NDYN * MTOT];
__device__ float g_b2d[N2P];
__device__ float g_ld4[16 * MTOT];        // per-4-dim-group logdet partials
__device__ int   g_dyn_map[NDYN];
__device__ int   g_stat_map[NSTA];
__device__ float g_stat_mv[NSTA];
__device__ int   g_pos[DTOT];             // d -> static position, or -1
__device__ int   g_n_dyn;
__device__ int   g_n_stat;

// ---------------- helpers ----------------
__device__ __forceinline__ float softplus_f(float v) {
    return fmaxf(v, 0.f) + log1pf(expf(-fabsf(v)));
}
__device__ __forceinline__ uint32_t smem_u32(const void* p) {
    uint32_t a;
    asm("{ .reg .u64 t; cvta.to.shared.u64 t, %1; cvt.u32.u64 %0, t; }" : "=r"(a) : "l"(p));
    return a;
}
__device__ __forceinline__ uint32_t packh(__half a, __half b) {
    __half2 t; t.x = a; t.y = b;
    return *(uint32_t*)&t;
}
__device__ __forceinline__ void split_h(float v, __half& hi, __half& lo) {
    hi = __float2half_rn(v);
    lo = __float2half_rn(v - __half2float(hi));
}
#define LDSM_X4(r0, r1, r2, r3, addr)                                          \
    asm volatile("ldmatrix.sync.aligned.m8n8.x4.shared.b16 {%0,%1,%2,%3}, [%4];" \
                 : "=r"(r0), "=r"(r1), "=r"(r2), "=r"(r3) : "r"(addr))
#define CP_ASYNC16(dst, src)                                                   \
    asm volatile("cp.async.cg.shared.global [%0], [%1], 16;" :: "r"(dst), "l"(src))
#define CP_COMMIT() asm volatile("cp.async.commit_group;" ::: "memory")

__device__ __forceinline__ void mma16816(float* d, const uint32_t* a,
                                         uint32_t b0, uint32_t b1) {
    asm volatile(
        "mma.sync.aligned.m16n8k16.row.col.f32.f16.f16.f32 "
        "{%0,%1,%2,%3}, {%4,%5,%6,%7}, {%8,%9}, {%0,%1,%2,%3};"
        : "+f"(d[0]), "+f"(d[1]), "+f"(d[2]), "+f"(d[3])
        : "r"(a[0]), "r"(a[1]), "r"(a[2]), "r"(a[3]), "r"(b0), "r"(b1));
}
// fp16-accumulating variant — used only for lo-correction terms
__device__ __forceinline__ void mma16816h(uint32_t* d, const uint32_t* a,
                                          uint32_t b0, uint32_t b1) {
    asm volatile(
        "mma.sync.aligned.m16n8k16.row.col.f16.f16.f16.f16 "
        "{%0,%1}, {%2,%3,%4,%5}, {%6,%7}, {%0,%1};"
        : "+r"(d[0]), "+r"(d[1])
        : "r"(a[0]), "r"(a[1]), "r"(a[2]), "r"(a[3]), "r"(b0), "r"(b1));
}

// ---------------- setup (parallel) ----------------
__global__ void k_setup(const float* __restrict__ mask) {
    __shared__ int pd[DTOT], ps[DTOT];
    __shared__ int s_nd, s_ns;
    int d = threadIdx.x;                      // 0..127
    float mv = mask[d];
    int isdyn = (mv == 0.0f) ? 1 : 0;
    pd[d] = isdyn;
    ps[d] = 1 - isdyn;
    __syncthreads();
    if (d == 0) {
        int cd = 0, cs = 0;
        for (int i = 0; i < DTOT; i++) {
            int t = pd[i]; pd[i] = cd; cd += t;
            int u = ps[i]; ps[i] = cs; cs += u;
        }
        s_nd = cd; s_ns = cs < NSTA ? cs : NSTA;
        g_n_dyn = cd; g_n_stat = s_ns;
    }
    __syncthreads();
    if (isdyn) {
        if (pd[d] < NDYN) g_dyn_map[pd[d]] = d;
        g_pos[d] = -1;
    } else {
        int p = ps[d];
        if (p < NSTA) { g_stat_map[p] = d; g_stat_mv[p] = mv; }
        g_pos[d] = (p < NSTA) ? p : -1;
    }
    int nd = s_nd, ns = s_ns;
    if (d < NDYN && d >= nd) g_dyn_map[d] = 0;
    if (d < NSTA && d >= ns) { g_stat_map[d] = 0; g_stat_mv[d] = 0.f; }
}

// ---- merged prep: cvtB + b2 + d8w(fp16) + W1 + passx ------------------------
#define NB_CVTB (48 * 8)
#define PB_BASE (NB_CVTB + 6 + 64 + 64)      // 518
#define NB_PASS ((MTOT * DTOT / 4) / 256)    // 4096
__global__ __launch_bounds__(256) void k_prep_all(const float* __restrict__ W2,
                                                  const float* __restrict__ b2,
                                                  const float* __restrict__ W1,
                                                  const float4* __restrict__ x4,
                                                  const float* __restrict__ mask,
                                                  float4* __restrict__ out4) {
    int bid = blockIdx.x, tid = threadIdx.x;
    if (bid >= PB_BASE) {
        int i = (bid - PB_BASE) * 256 + tid;
        float4 v = x4[i];
        int m = i >> 5;
        int c = (i & 31) * 4;
        float4 mk = *(const float4*)&mask[c];
        float4 o;
        o.x = v.x * mk.x; o.y = v.y * mk.y; o.z = v.z * mk.z; o.w = v.w * mk.w;
        out4[i] = o;
        const float* vv = (const float*)&v;
        const float* mm = (const float*)&mk;
#pragma unroll
        for (int j = 0; j < 4; j++) {
            int pos = g_pos[c + j];
            if (pos >= 0) {
                float sv = vv[j] * mm[j];
                __half hi, lo; split_h(sv, hi, lo);
                g_xs_hi[(size_t)m * NSTA + pos] = hi;
                g_xs_lo[(size_t)m * NSTA + pos] = lo;
            }
        }
    } else if (bid < NB_CVTB) {
        __shared__ float t[32][33];
        int n0 = (bid % 48) * 32, k0 = (bid / 48) * 32;
        int tx = tid & 31, ty = tid >> 5;
        int n = n0 + tx;
        int dd = n / NP2, j = n - dd * NP2;
        int col = (dd < g_n_dyn) ? (g_dyn_map[dd] * TOTP + j) : -1;
#pragma unroll
        for (int i = 0; i < 4; i++) {
            int k = k0 + ty + 8 * i;
            t[tx][ty + 8 * i] = (col >= 0) ? W2[(size_t)k * W2S + col] : 0.f;
        }
        __syncthreads();
#pragma unroll
        for (int i = 0; i < 4; i++) {
            int nn = n0 + ty + 8 * i;
            float v = t[ty + 8 * i][tx];
            __half hi, lo; split_h(v, hi, lo);
            g_wB_hi[(size_t)nn * HTOT + k0 + tx] = hi;
            g_wB_lo[(size_t)nn * HTOT + k0 + tx] = lo;
        }
    } else if (bid < NB_CVTB + 6) {
        int n = (bid - NB_CVTB) * 256 + tid;
        if (n < N2P) {
            int dd = n / NP2, j = n - dd * NP2;
            g_b2d[n] = (dd < g_n_dyn) ? b2[g_dyn_map[dd] * TOTP + j] : 0.f;
        }
    } else if (bid < NB_CVTB + 6 + 64) {
        int idx = (bid - NB_CVTB - 6) * 256 + tid;   // n*256+k
        int n = idx >> 8, k = idx & 255;
        float v = W2[(size_t)k * W2S + g_dyn_map[n] * TOTP + 24];
        __half hi, lo; split_h(v, hi, lo);
        g_wd8_hi[idx] = hi;
        g_wd8_lo[idx] = lo;
        if (idx < NDYN) g_b24[idx] = b2[g_dyn_map[idx] * TOTP + 24];
    } else {
        int idx = (bid - NB_CVTB - 6 - 64) * 256 + tid;
        int k = idx & 63, n = idx >> 6;
        float v = (k < g_n_stat) ? W1[(size_t)g_stat_map[k] * HTOT + n] : 0.f;
        __half hi, lo; split_h(v, hi, lo);
        g_w1_hi[(size_t)n * NSTA + k] = hi;
        g_w1_lo[(size_t)n * NSTA + k] = lo;
    }
}

// ---- GEMM1 via mma.sync fp16 3-term: hidden = relu(xs@w1^T + b1) ------------
#define O1_A_HI 0
#define O1_A_LO 16384
#define O1_B_HI 32768
#define O1_B_LO 49152
#define SM1_BYTES 65536

__global__ __launch_bounds__(256, 2) void k_gemm1(const float* __restrict__ b1) {
    extern __shared__ __align__(16) char smem[];
    const uint32_t sb = smem_u32(smem);
    const int tid = threadIdx.x, wid = tid >> 5, lane = tid & 31;
    const int mbase = blockIdx.x * 128, nbase = blockIdx.y * 128;
    const int warpM = wid & 3, warpN = wid >> 2;

    const int r_ld = tid >> 3, c_ld = tid & 7;
#pragma unroll
    for (int i = 0; i < 4; i++) {
        int r = r_ld + 32 * i;
        uint32_t sw = r * 128 + ((c_ld ^ (r & 7)) << 4);
        size_t ga = (size_t)(mbase + r) * NSTA + c_ld * 8;
        size_t gb = (size_t)(nbase + r) * NSTA + c_ld * 8;
        CP_ASYNC16(sb + O1_A_HI + sw, (const char*)&g_xs_hi[ga]);
        CP_ASYNC16(sb + O1_A_LO + sw, (const char*)&g_xs_lo[ga]);
        CP_ASYNC16(sb + O1_B_HI + sw, (const char*)&g_w1_hi[gb]);
        CP_ASYNC16(sb + O1_B_LO + sw, (const char*)&g_w1_lo[gb]);
    }
    CP_COMMIT();

    float acc[2][8][4];
#pragma unroll
    for (int mt = 0; mt < 2; mt++)
#pragma unroll
        for (int nt = 0; nt < 8; nt++)
#pragma unroll
            for (int r = 0; r < 4; r++) acc[mt][nt][r] = 0.f;

    const int tsel = lane >> 3, rowin = lane & 7;
    const int tshalf = (tsel & 1) * 8, tkhalf = tsel >> 1;

    asm volatile("cp.async.wait_group 0;" ::: "memory");
    __syncthreads();

#pragma unroll
    for (int s = 0; s < 4; ++s) {
        const int kch = s * 2 + tkhalf;
        uint32_t aH[2][4], aL[2][4];
#pragma unroll
        for (int mt = 0; mt < 2; mt++) {
            int r = warpM * 32 + mt * 16 + tshalf + rowin;
            uint32_t off = r * 128 + ((kch ^ (r & 7)) << 4);
            LDSM_X4(aH[mt][0], aH[mt][1], aH[mt][2], aH[mt][3], sb + O1_A_HI + off);
            LDSM_X4(aL[mt][0], aL[mt][1], aL[mt][2], aL[mt][3], sb + O1_A_LO + off);
        }
        uint32_t bH[8][2], bL[8][2];
#pragma unroll
        for (int ng = 0; ng < 4; ng++) {
            int r = warpN * 64 + ng * 16 + tshalf + rowin;
            uint32_t off = r * 128 + ((kch ^ (r & 7)) << 4);
            uint32_t q0, q1, q2, q3;
            LDSM_X4(q0, q1, q2, q3, sb + O1_B_HI + off);
            bH[ng * 2][0] = q0; bH[ng * 2 + 1][0] = q1;
            bH[ng * 2][1] = q2; bH[ng * 2 + 1][1] = q3;
            LDSM_X4(q0, q1, q2, q3, sb + O1_B_LO + off);
            bL[ng * 2][0] = q0; bL[ng * 2 + 1][0] = q1;
            bL[ng * 2][1] = q2; bL[ng * 2 + 1][1] = q3;
        }
#pragma unroll
        for (int mt = 0; mt < 2; mt++)
#pragma unroll
            for (int nt = 0; nt < 8; nt++) {
                mma16816(acc[mt][nt], aH[mt], bH[nt][0], bH[nt][1]);
                mma16816(acc[mt][nt], aH[mt], bL[nt][0], bL[nt][1]);
                mma16816(acc[mt][nt], aL[mt], bH[nt][0], bH[nt][1]);
            }
    }

    // epilogue: +b1, relu, fp16 split, store [m][h]
    const int mrow = warpM * 32 + (lane >> 2);
    const int ncol0 = warpN * 64 + 2 * (lane & 3);
    float bb[8][2];
#pragma unroll
    for (int nt = 0; nt < 8; nt++) {
        bb[nt][0] = __ldg(&b1[nbase + ncol0 + nt * 8]);
        bb[nt][1] = __ldg(&b1[nbase + ncol0 + nt * 8 + 1]);
    }
#pragma unroll
    for (int mt = 0; mt < 2; mt++) {
#pragma unroll
        for (int nt = 0; nt < 8; nt++) {
            int m0 = mbase + mrow + mt * 16;
            int c = nbase + ncol0 + nt * 8;
            float f0 = fmaxf(acc[mt][nt][0] + bb[nt][0], 0.f);
            float f1 = fmaxf(acc[mt][nt][1] + bb[nt][1], 0.f);
            float f2 = fmaxf(acc[mt][nt][2] + bb[nt][0], 0.f);
            float f3 = fmaxf(acc[mt][nt][3] + bb[nt][1], 0.f);
            __half h0, l0, h1, l1, h2, l2, h3, l3;
            split_h(f0, h0, l0); split_h(f1, h1, l1);
            split_h(f2, h2, l2); split_h(f3, h3, l3);
            *(uint32_t*)&g_hA_hi[(size_t)m0 * HTOT + c]       = packh(h0, h1);
            *(uint32_t*)&g_hA_lo[(size_t)m0 * HTOT + c]       = packh(l0, l1);
            *(uint32_t*)&g_hA_hi[(size_t)(m0 + 8) * HTOT + c] = packh(h2, h3);
            *(uint32_t*)&g_hA_lo[(size_t)(m0 + 8) * HTOT + c] = packh(l2, l3);
        }
    }
}

// ---- d8 via mma.sync fp16 3-term: g_d8[dd][m] = hidden@wd8^T + b24 ----------
#define OD_A_HI 0
#define OD_A_LO 16384
#define OD_B_HI 32768
#define OD_B_LO 40960
#define SMD_STG 49152
#define SMD_BYTES (2 * SMD_STG)   // 96KB -> 2 CTAs/SM

__global__ __launch_bounds__(256, 2) void k_d8_mma() {
    extern __shared__ __align__(16) char smem[];
    const uint32_t sb = smem_u32(smem);
    const int tid = threadIdx.x, wid = tid >> 5, lane = tid & 31;
    const int mbase = blockIdx.x * 128;
    const int warpM = wid & 3, warpN = wid >> 2;

    float acc[2][4][4];
#pragma unroll
    for (int mt = 0; mt < 2; mt++)
#pragma unroll
        for (int nt = 0; nt < 4; nt++)
#pragma unroll
            for (int r = 0; r < 4; r++) acc[mt][nt][r] = 0.f;

    const int tsel = lane >> 3, rowin = lane & 7;
    const int tshalf = (tsel & 1) * 8, tkhalf = tsel >> 1;
    const int r_ld = tid >> 3, c_ld = tid & 7;

    auto prefetch = [&](int kc, int b) {
        uint32_t base = sb + b * SMD_STG;
#pragma unroll
        for (int i = 0; i < 4; i++) {
            int r = r_ld + 32 * i;
            uint32_t sw = r * 128 + ((c_ld ^ (r & 7)) << 4);
            size_t ga = (size_t)(mbase + r) * HTOT + kc * 64 + c_ld * 8;
            CP_ASYNC16(base + OD_A_HI + sw, (const char*)&g_hA_hi[ga]);
            CP_ASYNC16(base + OD_A_LO + sw, (const char*)&g_hA_lo[ga]);
        }
#pragma unroll
        for (int i = 0; i < 2; i++) {
            int r = r_ld + 32 * i;
            uint32_t sw = r * 128 + ((c_ld ^ (r & 7)) << 4);
            size_t gb = (size_t)r * HTOT + kc * 64 + c_ld * 8;
            CP_ASYNC16(base + OD_B_HI + sw, (const char*)&g_wd8_hi[gb]);
            CP_ASYNC16(base + OD_B_LO + sw, (const char*)&g_wd8_lo[gb]);
        }
        CP_COMMIT();
    };

    prefetch(0, 0);
#pragma unroll 1
    for (int kc = 0; kc < 4; ++kc) {
        if (kc < 3) {
            prefetch(kc + 1, (kc + 1) & 1);
            asm volatile("cp.async.wait_group 1;" ::: "memory");
        } else {
            asm volatile("cp.async.wait_group 0;" ::: "memory");
        }
        __syncthreads();
        const uint32_t base = sb + (kc & 1) * SMD_STG;
#pragma unroll
        for (int s = 0; s < 4; ++s) {
            const int kch = s * 2 + tkhalf;
            uint32_t aH[2][4], aL[2][4];
#pragma unroll
            for (int mt = 0; mt < 2; mt++) {
                int r = warpM * 32 + mt * 16 + tshalf + rowin;
                uint32_t off = r * 128 + ((kch ^ (r & 7)) << 4);
                LDSM_X4(aH[mt][0], aH[mt][1], aH[mt][2], aH[mt][3], base + OD_A_HI + off);
                LDSM_X4(aL[mt][0], aL[mt][1], aL[mt][2], aL[mt][3], base + OD_A_LO + off);
            }
            uint32_t bH[4][2], bL[4][2];
#pragma unroll
            for (int ng = 0; ng < 2; ng++) {
                int r = warpN * 32 + ng * 16 + tshalf + rowin;
                uint32_t off = r * 128 + ((kch ^ (r & 7)) << 4);
                uint32_t q0, q1, q2, q3;
                LDSM_X4(q0, q1, q2, q3, base + OD_B_HI + off);
                bH[ng * 2][0] = q0; bH[ng * 2 + 1][0] = q1;
                bH[ng * 2][1] = q2; bH[ng * 2 + 1][1] = q3;
                LDSM_X4(q0, q1, q2, q3, base + OD_B_LO + off);
                bL[ng * 2][0] = q0; bL[ng * 2 + 1][0] = q1;
                bL[ng * 2][1] = q2; bL[ng * 2 + 1][1] = q3;
            }
#pragma unroll
            for (int mt = 0; mt < 2; mt++)
#pragma unroll
                for (int nt = 0; nt < 4; nt++) {
                    mma16816(acc[mt][nt], aH[mt], bH[nt][0], bH[nt][1]);
                    mma16816(acc[mt][nt], aH[mt], bL[nt][0], bL[nt][1]);
                    mma16816(acc[mt][nt], aL[mt], bH[nt][0], bH[nt][1]);
                }
        }
        __syncthreads();   // load-bearing: next iter's prefetch overwrites buf (kc&1)
    }

    const int mrow = warpM * 32 + (lane >> 2);
    const int ncol0 = warpN * 32 + 2 * (lane & 3);
#pragma unroll
    for (int mt = 0; mt < 2; mt++) {
#pragma unroll
        for (int nt = 0; nt < 4; nt++) {
            int m0 = mbase + mrow + mt * 16;
            int n = ncol0 + nt * 8;
            float b0 = g_b24[n], b1v = g_b24[n + 1];
            g_d8[(size_t)n * MTOT + m0]           = acc[mt][nt][0] + b0;
            g_d8[(size_t)(n + 1) * MTOT + m0]     = acc[mt][nt][1] + b1v;
            g_d8[(size_t)n * MTOT + m0 + 8]       = acc[mt][nt][2] + b0;
            g_d8[(size_t)(n + 1) * MTOT + m0 + 8] = acc[mt][nt][3] + b1v;
        }
    }
}

// ---- GEMM2 (fp16 3-term, corrections in fp16-acc HMMA) + fused spline -------
#define STG 57344
#define OFF_A_HI 0
#define OFF_A_LO 16384
#define OFF_B_HI 32768
#define OFF_B_LO 45056
#define SM2_BYTES (2 * STG)
#define SMF_LD  (96 * 132)     // float offset of logdet-partial region

__global__ __launch_bounds__(256, 2) void k_gemm2_fused(const float* __restrict__ x,
                                                        float* __restrict__ out) {
    extern __shared__ __align__(16) char smem[];
    const uint32_t sb = smem_u32(smem);
    const int tid = threadIdx.x, wid = tid >> 5, lane = tid & 31;
    const int mbase = blockIdx.x * 128, nbase = blockIdx.y * NTILE;
    const int warpM = wid & 3, warpN = wid >> 2;

    float acc[2][6][4];         // main hi*hi term, fp32 acc
    uint32_t accC[2][6][2];     // corrections (hi*lo + lo*hi), fp16x2 acc
#pragma unroll
    for (int mt = 0; mt < 2; mt++)
#pragma unroll
        for (int nt = 0; nt < 6; nt++) {
#pragma unroll
            for (int r = 0; r < 4; r++) acc[mt][nt][r] = 0.f;
            accC[mt][nt][0] = 0u; accC[mt][nt][1] = 0u;
        }

    const int tsel = lane >> 3, rowin = lane & 7;
    const int tshalf = (tsel & 1) * 8, tkhalf = tsel >> 1;
    const int r_ld = tid >> 3, c_ld = tid & 7;

    auto prefetch = [&](int kc, int b) {
        uint32_t base = sb + b * STG;
#pragma unroll
        for (int i = 0; i < 4; i++) {
            int r = r_ld + 32 * i;
            uint32_t sw = r * 128 + ((c_ld ^ (r & 7)) << 4);
            size_t ga = (size_t)(mbase + r) * HTOT + kc * 64 + c_ld * 8;
            CP_ASYNC16(base + OFF_A_HI + sw, (const char*)&g_hA_hi[ga]);
            CP_ASYNC16(base + OFF_A_LO + sw, (const char*)&g_hA_lo[ga]);
        }
#pragma unroll
        for (int i = 0; i < 3; i++) {
            int r = r_ld + 32 * i;
            uint32_t sw = r * 128 + ((c_ld ^ (r & 7)) << 4);
            size_t gb = (size_t)(nbase + r) * HTOT + kc * 64 + c_ld * 8;
            CP_ASYNC16(base + OFF_B_HI + sw, (const char*)&g_wB_hi[gb]);
            CP_ASYNC16(base + OFF_B_LO + sw, (const char*)&g_wB_lo[gb]);
        }
        CP_COMMIT();
    };

    prefetch(0, 0);
#pragma unroll 1
    for (int kc = 0; kc < 4; ++kc) {
        if (kc < 3) {
            prefetch(kc + 1, (kc + 1) & 1);
            asm volatile("cp.async.wait_group 1;" ::: "memory");
        } else {
            asm volatile("cp.async.wait_group 0;" ::: "memory");
        }
        __syncthreads();
        const uint32_t base = sb + (kc & 1) * STG;
#pragma unroll
        for (int s = 0; s < 4; ++s) {
            const int kch = s * 2 + tkhalf;
            uint32_t aH[2][4], aL[2][4];
#pragma unroll
            for (int mt = 0; mt < 2; mt++) {
                int r = warpM * 32 + mt * 16 + tshalf + rowin;
                uint32_t off = r * 128 + ((kch ^ (r & 7)) << 4);
                LDSM_X4(aH[mt][0], aH[mt][1], aH[mt][2], aH[mt][3], base + OFF_A_HI + off);
                LDSM_X4(aL[mt][0], aL[mt][1], aL[mt][2], aL[mt][3], base + OFF_A_LO + off);
            }
            // load B per-ng to cap register pressure
#pragma unroll
            for (int ng = 0; ng < 3; ng++) {
                int r = warpN * 48 + ng * 16 + tshalf + rowin;
                uint32_t off = r * 128 + ((kch ^ (r & 7)) << 4);
                uint32_t bh0, bh1, bh2, bh3, bl0, bl1, bl2, bl3;
                LDSM_X4(bh0, bh1, bh2, bh3, base + OFF_B_HI + off);
                LDSM_X4(bl0, bl1, bl2, bl3, base + OFF_B_LO + off);
#pragma unroll
                for (int mt = 0; mt < 2; mt++) {
                    mma16816(acc[mt][ng * 2],     aH[mt], bh0, bh2);
                    mma16816(acc[mt][ng * 2 + 1], aH[mt], bh1, bh3);
                    mma16816h(accC[mt][ng * 2],     aH[mt], bl0, bl2);
                    mma16816h(accC[mt][ng * 2 + 1], aH[mt], bl1, bl3);
                    mma16816h(accC[mt][ng * 2],     aL[mt], bh0, bh2);
                    mma16816h(accC[mt][ng * 2 + 1], aL[mt], bh1, bh3);
                }
            }
        }
        __syncthreads();   // load-bearing: next iter's prefetch overwrites buf (kc&1)
    }

    // -------- stage D + corrections + bias into smem [n][m], stride 132 ------
    float* smf = (float*)smem;
    {
        int mrow = warpM * 32 + (lane >> 2);
        int ncol = 2 * (lane & 3);
#pragma unroll
        for (int mt = 0; mt < 2; mt++)
#pragma unroll
            for (int nt = 0; nt < 6; nt++) {
                int m = mrow + mt * 16;
                int n = warpN * 48 + nt * 8 + ncol;
                float b0 = g_b2d[nbase + n], b1v = g_b2d[nbase + n + 1];
                __half2 c01 = *(__half2*)&accC[mt][nt][0];
                __half2 c23 = *(__half2*)&accC[mt][nt][1];
                smf[n * 132 + m]           = acc[mt][nt][0] + __half2float(c01.x) + b0;
                smf[(n + 1) * 132 + m]     = acc[mt][nt][1] + __half2float(c01.y) + b1v;
                smf[n * 132 + m + 8]       = acc[mt][nt][2] + __half2float(c23.x) + b0;
                smf[(n + 1) * 132 + m + 8] = acc[mt][nt][3] + __half2float(c23.y) + b1v;
            }
    }
    __syncthreads();

    // -------- fused rational-quadratic spline: 4 dyn dims x 128 rows ---------
    const int m_l = tid & 127;
    const int m = mbase + m_l;
    float myld = 0.f;
#pragma unroll 1
    for (int i = 0; i < 2; ++i) {
        int ddl = (tid >> 7) + 2 * i;
        int dd = blockIdx.y * 4 + ddl;
        if (dd >= g_n_dyn) continue;
        int d = g_dyn_map[dd];
        float xd = x[(size_t)m * DTOT + d];
        float d8 = g_d8[(size_t)dd * MTOT + m];

        const float* u = &smf[(ddl * NP2) * 132 + m_l];
#define U(j) u[(j) * 132]
        float w[8], cw[9], h[8], ch[9];
        {
            float mx = U(0);
#pragma unroll
            for (int t = 1; t < 8; t++) mx = fmaxf(mx, U(t));
            float e[8], s = 0.f;
#pragma unroll
            for (int t = 0; t < 8; t++) { e[t] = expf(U(t) - mx); s += e[t]; }
            float inv = 1.f / s, c = 0.f;
            cw[0] = -3.f;
#pragma unroll
            for (int t = 0; t < 8; t++) {
                w[t] = 0.001f + 0.992f * e[t] * inv;
                c += w[t];
                cw[t + 1] = (c - 0.5f) * 6.f;
            }
            cw[8] += 1e-6f;
        }
        {
            float mx = U(8);
#pragma unroll
            for (int t = 1; t < 8; t++) mx = fmaxf(mx, U(8 + t));
            float e[8], s = 0.f;
#pragma unroll
            for (int t = 0; t < 8; t++) { e[t] = expf(U(8 + t) - mx); s += e[t]; }
            float inv = 1.f / s, c = 0.f;
            ch[0] = -3.f;
#pragma unroll
            for (int t = 0; t < 8; t++) {
                h[t] = 0.001f + 0.992f * e[t] * inv;
                c += h[t];
                ch[t + 1] = (c - 0.5f) * 6.f;
            }
        }
        int idx = -1;
#pragma unroll
        for (int t = 0; t < 9; t++) idx += (xd >= cw[t]) ? 1 : 0;
        idx = max(0, min(7, idx));

        float ww = w[0], cwi = cw[0], hh = h[0], chi = ch[0], ud0 = U(16), ud1 = U(17);
#pragma unroll
        for (int t = 1; t < 8; t++) {
            bool sel = (idx == t);
            ww  = sel ? w[t]      : ww;
            cwi = sel ? cw[t]     : cwi;
            hh  = sel ? h[t]      : hh;
            chi = sel ? ch[t]     : chi;
            ud0 = sel ? U(16 + t) : ud0;
            ud1 = sel ? ((t == 7) ? d8 : U(17 + t)) : ud1;
        }
#undef U
        float di  = fminf(fmaxf(softplus_f(ud0) + 0.001f, 0.001f), 1000.f);
        float di1 = fminf(fmaxf(softplus_f(ud1) + 0.001f, 0.001f), 1000.f);

        float delta = hh / ww;
        float th = fminf(fmaxf((xd - cwi) / ww, 0.f), 1.f);
        float t1m = th * (1.f - th);
        float th2 = th * th;
        float num = di1 * th2 + delta * t1m;
        float den = fmaxf(delta + (di + di1 - 2.f * delta) * t1m, 1e-6f);
        float sp  = chi + delta * num / den * ww;
        float omth = 1.f - th;
        float dnum = delta * delta * (di1 * th2 + 2.f * delta * t1m + di * omth * omth);
        float sld = logf(fmaxf(dnum / (den * den), 1e-12f));

        bool inr = (xd >= -3.f) && (xd <= 3.f);
        out[(size_t)m * DTOT + d] = inr ? sp : xd;
        myld += inr ? sld : 0.f;
    }
    // per-4-dim-group logdet partial (deterministic fixed order)
    smf[SMF_LD + tid] = myld;
    __syncthreads();
    if (tid < 128)
        g_ld4[(size_t)blockIdx.y * MTOT + m] = smf[SMF_LD + tid] + smf[SMF_LD + tid + 128];
}

// ---------------- deterministic pairwise-tree logdet reduction (16 rows) -----
__global__ void k_reduce(float* __restrict__ outld) {
    int m = blockIdx.x * 256 + threadIdx.x;
    float a[8];
#pragma unroll
    for (int i = 0; i < 8; i++)
        a[i] = g_ld4[(size_t)(2 * i) * MTOT + m] + g_ld4[(size_t)(2 * i + 1) * MTOT + m];
#pragma unroll
    for (int w = 4; w >= 1; w >>= 1)
#pragma unroll
        for (int i = 0; i < w; i++) a[i] = a[2 * i] + a[2 * i + 1];
    outld[m] = a[0];
}

extern "C" void kernel_launch(void* const* d_in, const int* in_sizes, int n_in,
                              void* d_out, int out_size) {
    const float* x    = (const float*)d_in[0];
    const float* mask = (const float*)d_in[1];
    const float* W1   = (const float*)d_in[2];
    const float* b1   = (const float*)d_in[3];
    const float* W2   = (const float*)d_in[4];
    const float* b2   = (const float*)d_in[5];
    float* out = (float*)d_out;

    cudaFuncSetAttribute(k_gemm1, cudaFuncAttributeMaxDynamicSharedMemorySize, SM1_BYTES);
    cudaFuncSetAttribute(k_d8_mma, cudaFuncAttributeMaxDynamicSharedMemorySize, SMD_BYTES);
    cudaFuncSetAttribute(k_gemm2_fused, cudaFuncAttributeMaxDynamicSharedMemorySize, SM2_BYTES);

    k_setup<<<1, DTOT>>>(mask);
    k_prep_all<<<PB_BASE + NB_PASS, 256>>>(W2, b2, W1, (const float4*)x, mask,
                                           (float4*)out);
    k_gemm1<<<dim3(MTOT / 128, HTOT / 128), 256, SM1_BYTES>>>(b1);
    k_d8_mma<<<MTOT / 128, 256, SMD_BYTES>>>();
    k_gemm2_fused<<<dim3(MTOT / 128, N2P / NTILE), 256, SM2_BYTES>>>(x, out);
    if (out_size >= MTOT * DTOT + MTOT)
        k_reduce<<<MTOT / 256, 256>>>(out + (size_t)MTOT * DTOT);
}